// round 1
// baseline (speedup 1.0000x reference)
#include <cuda_runtime.h>

#define KDIM 512
#define DDIM 1024
#define KK (KDIM*KDIM)
#define LMBDA 1000.0f
#define NITER 50

// ---------------- device scratch (no allocations allowed) ----------------
__device__ float g_Ga[KK];        // A^T A
__device__ float g_Gb[KK];        // B^T B
__device__ float g_B0[KK];        // rhs dir0 = B^T A  [Kb,Ka]
__device__ float g_B1[KK];        // rhs dir1 = A^T B  [Ka,Kb]
__device__ float g_mask[2*KK];
__device__ float g_invM[2*KK];
__device__ float g_R[2*KK];
__device__ float g_P[2*KK];
__device__ float g_S[2*KK];
__device__ float g_rz[2*KDIM];
__device__ float g_smax;

// ---------------- helpers ----------------
__device__ __forceinline__ float blockReduce256(float v, float* sh) {
    #pragma unroll
    for (int o = 16; o > 0; o >>= 1) v += __shfl_xor_sync(0xffffffffu, v, o);
    int w = threadIdx.x >> 5;
    if ((threadIdx.x & 31) == 0) sh[w] = v;
    __syncthreads();
    if (threadIdx.x < 32) {
        float r = (threadIdx.x < 8) ? sh[threadIdx.x] : 0.f;
        #pragma unroll
        for (int o = 4; o > 0; o >>= 1) r += __shfl_xor_sync(0xffffffffu, r, o);
        if (threadIdx.x == 0) sh[0] = r;
    }
    __syncthreads();
    float out = sh[0];
    __syncthreads();
    return out;
}

// ---------------- K1: joint max eigenvalue ----------------
__global__ void kmax(const float* __restrict__ ea, const float* __restrict__ eb) {
    __shared__ float sm[256];
    int t = threadIdx.x;
    float m = 0.f;
    for (int i = t; i < KDIM; i += 256) { m = fmaxf(m, ea[i]); m = fmaxf(m, eb[i]); }
    sm[t] = m; __syncthreads();
    for (int s = 128; s > 0; s >>= 1) { if (t < s) sm[t] = fmaxf(sm[t], sm[t + s]); __syncthreads(); }
    if (t == 0) g_smax = sm[0];
}

// ---------------- K2: resolvent masks (GAMMA=1) ----------------
__global__ void kmask(const float* __restrict__ ea, const float* __restrict__ eb) {
    int idx = blockIdx.x * blockDim.x + threadIdx.x;
    if (idx >= 2 * KK) return;
    int d = idx / KK;
    int rem = idx - d * KK;
    int r = rem >> 9, c = rem & (KDIM - 1);
    float s = g_smax;
    // dir0: mask_ab = _compute_mask(ea, eb): rows<-eb, cols<-ea
    // dir1: mask_ba = _compute_mask(eb, ea): rows<-ea, cols<-eb
    const float* er = (d == 0) ? eb : ea;
    const float* ec = (d == 0) ? ea : eb;
    float gb = er[r] / s, ga = ec[c] / s;
    float gb2 = gb * gb + 1.f, ga2 = ga * ga + 1.f;
    float mre = gb / gb2 - ga / ga2;
    float mim = 1.f / gb2 - 1.f / ga2;
    g_mask[idx] = mre * mre + mim * mim;
}

// ---------------- K3: C = X^T Y, X,Y: [D, K] row-major, 4 combos via z ----------------
__global__ void __launch_bounds__(256) gemm_tn(const float* __restrict__ A,
                                               const float* __restrict__ Bm) {
    int z = blockIdx.z;
    const float* X; const float* Y; float* Cp;
    if (z == 0)      { X = A;  Y = A;  Cp = g_Ga; }
    else if (z == 1) { X = Bm; Y = Bm; Cp = g_Gb; }
    else if (z == 2) { X = Bm; Y = A;  Cp = g_B0; }
    else             { X = A;  Y = Bm; Cp = g_B1; }

    __shared__ float As[16][64];
    __shared__ float Bs[16][64];
    int tid = threadIdx.x;
    int tx = tid & 15, ty = tid >> 4;
    int m0 = blockIdx.x * 64, n0 = blockIdx.y * 64;
    int lr = tid >> 4, lc = (tid & 15) * 4;

    float acc[4][4] = {};
    for (int k0 = 0; k0 < DDIM; k0 += 16) {
        *(float4*)&As[lr][lc] = *(const float4*)&X[(k0 + lr) * KDIM + m0 + lc];
        *(float4*)&Bs[lr][lc] = *(const float4*)&Y[(k0 + lr) * KDIM + n0 + lc];
        __syncthreads();
        #pragma unroll
        for (int kk = 0; kk < 16; kk++) {
            float a[4], b[4];
            *(float4*)a = *(float4*)&As[kk][ty * 4];
            *(float4*)b = *(float4*)&Bs[kk][tx * 4];
            #pragma unroll
            for (int i = 0; i < 4; i++)
                #pragma unroll
                for (int j = 0; j < 4; j++) acc[i][j] += a[i] * b[j];
        }
        __syncthreads();
    }
    #pragma unroll
    for (int i = 0; i < 4; i++) {
        float4 o; o.x = acc[i][0]; o.y = acc[i][1]; o.z = acc[i][2]; o.w = acc[i][3];
        *(float4*)&Cp[(m0 + ty * 4 + i) * KDIM + n0 + tx * 4] = o;
    }
}

// ---------------- K4: PCG init (x=0, r=b, z=invM*r, p=z, rz=r.z) ----------------
__global__ void __launch_bounds__(256) kinit(float* __restrict__ out) {
    __shared__ float sh[8];
    int blk = blockIdx.x;              // 0..1023
    int dir = blk >> 9, row = blk & 511;
    int base = dir * KK + row * KDIM;
    const float* b = ((dir == 0) ? g_B0 : g_B1) + row * KDIM;
    const float* G = (dir == 0) ? g_Ga : g_Gb;
    const float* m = g_mask + base;
    float* invM = g_invM + base;
    float* R = g_R + base;
    float* P = g_P + base;
    float* X = out + base;
    int t = threadIdx.x;
    float part = 0.f;
    #pragma unroll
    for (int q = 0; q < 2; q++) {
        int k = t + q * 256;
        float im = 1.f / (G[k * KDIM + k] + LMBDA * m[k]);
        float r = b[k];
        float z = im * r;
        invM[k] = im; R[k] = r; P[k] = z; X[k] = 0.f;
        part += r * z;
    }
    float rz = blockReduce256(part, sh);
    if (t == 0) g_rz[blk] = rz;
}

// ---------------- K5: S = P @ G + LMBDA * (mask .* P), batched over dir ----------------
__global__ void __launch_bounds__(256) gemm_iter() {
    int dir = blockIdx.z;
    const float* P  = g_P + dir * KK;
    const float* G  = (dir == 0) ? g_Ga : g_Gb;
    const float* Mk = g_mask + dir * KK;
    float* S = g_S + dir * KK;

    __shared__ float Ps[16][68];  // transposed tile, padded
    __shared__ float Gs[16][64];
    int tid = threadIdx.x;
    int tx = tid & 15, ty = tid >> 4;
    int m0 = blockIdx.x * 64, n0 = blockIdx.y * 64;
    int lr = tid >> 4, lc = (tid & 15) * 4;     // G loader
    int pr = tid >> 2, pc = (tid & 3) * 4;      // P loader (64x16 tile)

    float acc[4][4] = {};
    for (int j0 = 0; j0 < KDIM; j0 += 16) {
        float4 pv = *(const float4*)&P[(m0 + pr) * KDIM + j0 + pc];
        Ps[pc + 0][pr] = pv.x; Ps[pc + 1][pr] = pv.y;
        Ps[pc + 2][pr] = pv.z; Ps[pc + 3][pr] = pv.w;
        *(float4*)&Gs[lr][lc] = *(const float4*)&G[(j0 + lr) * KDIM + n0 + lc];
        __syncthreads();
        #pragma unroll
        for (int kk = 0; kk < 16; kk++) {
            float a[4], b[4];
            *(float4*)a = *(float4*)&Ps[kk][ty * 4];
            *(float4*)b = *(float4*)&Gs[kk][tx * 4];
            #pragma unroll
            for (int i = 0; i < 4; i++)
                #pragma unroll
                for (int j = 0; j < 4; j++) acc[i][j] += a[i] * b[j];
        }
        __syncthreads();
    }
    // fused epilogue: + LMBDA * mask .* P
    #pragma unroll
    for (int i = 0; i < 4; i++) {
        int row = m0 + ty * 4 + i;
        int col = n0 + tx * 4;
        float4 p4 = *(const float4*)&P[row * KDIM + col];
        float4 m4 = *(const float4*)&Mk[row * KDIM + col];
        float4 o;
        o.x = acc[i][0] + LMBDA * m4.x * p4.x;
        o.y = acc[i][1] + LMBDA * m4.y * p4.y;
        o.z = acc[i][2] + LMBDA * m4.z * p4.z;
        o.w = acc[i][3] + LMBDA * m4.w * p4.w;
        *(float4*)&S[row * KDIM + col] = o;
    }
}

// ---------------- K6: per-system PCG update (one block per system) ----------------
__global__ void __launch_bounds__(256) kupdate(float* __restrict__ out) {
    __shared__ float sh[8];
    int blk = blockIdx.x;
    int dir = blk >> 9, row = blk & 511;
    int base = dir * KK + row * KDIM;
    float* P = g_P + base;
    float* S = g_S + base;
    float* R = g_R + base;
    float* X = out + base;
    const float* invM = g_invM + base;
    int t = threadIdx.x;

    float p0 = P[t], p1 = P[t + 256];
    float s0 = S[t], s1 = S[t + 256];
    float ps = blockReduce256(p0 * s0 + p1 * s1, sh);
    float rz_old = g_rz[blk];
    float alpha = rz_old / fmaxf(ps, 1e-30f);

    float r0 = R[t]       - alpha * s0;
    float r1 = R[t + 256] - alpha * s1;
    X[t]       += alpha * p0;
    X[t + 256] += alpha * p1;
    float z0 = invM[t] * r0, z1 = invM[t + 256] * r1;
    float rz = blockReduce256(r0 * z0 + r1 * z1, sh);
    float beta = rz / fmaxf(rz_old, 1e-30f);

    P[t]       = z0 + beta * p0;
    P[t + 256] = z1 + beta * p1;
    R[t] = r0; R[t + 256] = r1;
    if (t == 0) g_rz[blk] = rz;
}

// ---------------- launch ----------------
extern "C" void kernel_launch(void* const* d_in, const int* in_sizes, int n_in,
                              void* d_out, int out_size) {
    const float* A  = (const float*)d_in[0];  // sdescr_a [1024,512]
    const float* Bm = (const float*)d_in[1];  // sdescr_b [1024,512]
    const float* ea = (const float*)d_in[2];  // evals_a [512]
    const float* eb = (const float*)d_in[3];  // evals_b [512]
    float* out = (float*)d_out;               // [2,512,512]: fmap_12 then fmap_21

    kmax<<<1, 256>>>(ea, eb);
    kmask<<<(2 * KK + 255) / 256, 256>>>(ea, eb);
    {
        dim3 g(8, 8, 4);
        gemm_tn<<<g, 256>>>(A, Bm);
    }
    kinit<<<1024, 256>>>(out);
    for (int it = 0; it < NITER; it++) {
        dim3 g(8, 8, 2);
        gemm_iter<<<g, 256>>>();
        kupdate<<<1024, 256>>>(out);
    }
}